// round 13
// baseline (speedup 1.0000x reference)
#include <cuda_runtime.h>
#include <math_constants.h>

// LLaDA2 group-limited router, GB300 sm_103a — round 13.
// R7 base (best-profiled). Extraction loop replaced by a 3-level cross-lane
// tie-aware merge tree (shfl distances 1,2,4): after it, every octet lane
// holds the identical global sorted top-8, and lane sub muxes out element
// sub. Removes the 8-round serial shfl dependency chain (~700 -> ~230 cyc).

#define NUM_EXPERTS 256
#define TOPK 8
#define TOPKG 4
#define ROUTER_SCALE 2.5f
#define NEG_INF (-CUDART_INF_F)

#define GROW 36                 // floats per padded 32-expert group row (144B)
#define TROW (8 * GROW)
#define WROWS (4 * TROW)
#define NWARPS 4                // 128 threads per block

// ---- scalar keyed CE (descending); ties keep first arg ----
static __device__ __forceinline__ void cef(float& ka, unsigned& xa,
                                           float& kb, unsigned& xb) {
    float kx = fmaxf(ka, kb);
    float kn = fminf(ka, kb);
    bool t = (kb > ka);
    unsigned ix = t ? xb : xa;
    unsigned in_ = t ? xa : xb;
    ka = kx; kb = kn; xa = ix; xb = in_;
}
static __device__ __forceinline__ void maxsel(float& lk, unsigned& li,
                                              float ck, unsigned ci) {
    bool t = (ck > lk);
    lk = fmaxf(lk, ck);
    li = t ? ci : li;
}
// ---- tie-aware CE: (kb>ka) || (kb==ka && xb<xa); symmetric & exact ----
static __device__ __forceinline__ void cet(float& ka, unsigned& xa,
                                           float& kb, unsigned& xb) {
    bool t = (kb > ka) || (kb == ka && xb < xa);
    float nka = t ? kb : ka;
    float nkb = t ? ka : kb;
    unsigned nxa = t ? xb : xa;
    unsigned nxb = t ? xa : xb;
    ka = nka; kb = nkb; xa = nxa; xb = nxb;
}
static __device__ __forceinline__ void maxselt(float& lk, unsigned& li,
                                               float ck, unsigned ci) {
    bool t = (ck > lk) || (ck == lk && ci < li);
    lk = t ? ck : lk;
    li = t ? ci : li;
}

// Batcher 8-input sorting network (19 CE), descending.
static __device__ __forceinline__ void sort8(float k[8], unsigned x[8]) {
    cef(k[0],x[0],k[1],x[1]); cef(k[2],x[2],k[3],x[3]);
    cef(k[4],x[4],k[5],x[5]); cef(k[6],x[6],k[7],x[7]);
    cef(k[0],x[0],k[2],x[2]); cef(k[1],x[1],k[3],x[3]);
    cef(k[4],x[4],k[6],x[6]); cef(k[5],x[5],k[7],x[7]);
    cef(k[1],x[1],k[2],x[2]); cef(k[5],x[5],k[6],x[6]);
    cef(k[0],x[0],k[4],x[4]); cef(k[1],x[1],k[5],x[5]);
    cef(k[2],x[2],k[6],x[6]); cef(k[3],x[3],k[7],x[7]);
    cef(k[2],x[2],k[4],x[4]); cef(k[3],x[3],k[5],x[5]);
    cef(k[1],x[1],k[2],x[2]); cef(k[3],x[3],k[4],x[4]); cef(k[5],x[5],k[6],x[6]);
}

// L := top-8 of L ∪ C (both sorted desc): 8 max-selects + 12-CE bitonic clean.
static __device__ __forceinline__ void merge8(float Lk[8], unsigned Li[8],
                                              const float Ck[8], const unsigned Ci[8]) {
#pragma unroll
    for (int i = 0; i < 8; ++i) maxsel(Lk[i], Li[i], Ck[7 - i], Ci[7 - i]);
    cef(Lk[0],Li[0],Lk[4],Li[4]); cef(Lk[1],Li[1],Lk[5],Li[5]);
    cef(Lk[2],Li[2],Lk[6],Li[6]); cef(Lk[3],Li[3],Lk[7],Li[7]);
    cef(Lk[0],Li[0],Lk[2],Li[2]); cef(Lk[1],Li[1],Lk[3],Li[3]);
    cef(Lk[4],Li[4],Lk[6],Li[6]); cef(Lk[5],Li[5],Lk[7],Li[7]);
    cef(Lk[0],Li[0],Lk[1],Li[1]); cef(Lk[2],Li[2],Lk[3],Li[3]);
    cef(Lk[4],Li[4],Lk[5],Li[5]); cef(Lk[6],Li[6],Lk[7],Li[7]);
}
// Tie-aware variant (cross-lane merges; symmetric so all lanes agree).
static __device__ __forceinline__ void merge8t(float Lk[8], unsigned Li[8],
                                               const float Ck[8], const unsigned Ci[8]) {
#pragma unroll
    for (int i = 0; i < 8; ++i) maxselt(Lk[i], Li[i], Ck[7 - i], Ci[7 - i]);
    cet(Lk[0],Li[0],Lk[4],Li[4]); cet(Lk[1],Li[1],Lk[5],Li[5]);
    cet(Lk[2],Li[2],Lk[6],Li[6]); cet(Lk[3],Li[3],Lk[7],Li[7]);
    cet(Lk[0],Li[0],Lk[2],Li[2]); cet(Lk[1],Li[1],Lk[3],Li[3]);
    cet(Lk[4],Li[4],Lk[6],Li[6]); cet(Lk[5],Li[5],Lk[7],Li[7]);
    cet(Lk[0],Li[0],Lk[1],Li[1]); cet(Lk[2],Li[2],Lk[3],Li[3]);
    cet(Lk[4],Li[4],Lk[5],Li[5]); cet(Lk[6],Li[6],Lk[7],Li[7]);
}

static __device__ __forceinline__ float sigmoid_fast(float x) {
    float e = __expf(-x);
    float d = 1.0f + e;
    float r;
    asm("rcp.approx.f32 %0, %1;" : "=f"(r) : "f"(d));
    return r;
}

__global__ void __launch_bounds__(128)
router_kernel(const float* __restrict__ logits,
              const float* __restrict__ bias,
              float* __restrict__ out_w,
              float* __restrict__ out_i,
              int T) {
    __shared__ float skey[NWARPS * WROWS];   // 18432 B

    const int warp = threadIdx.x >> 5;
    const int lane = threadIdx.x & 31;
    float* wk = skey + warp * WROWS;

    const int tok0 = blockIdx.x * (NWARPS * 4) + warp * 4;

    float4 bv0 = __ldg((const float4*)(bias + lane * 8));
    float4 bv1 = __ldg((const float4*)(bias + lane * 8 + 4));
    float bb[8] = {bv0.x, bv0.y, bv0.z, bv0.w, bv1.x, bv1.y, bv1.z, bv1.w};

    const int g_mine = lane >> 2;
    const int q = lane & 3;

    // ---- Pass A (coalesced): keys -> smem; exact group top-2 scores ----
    float gs_t[4];
#pragma unroll
    for (int t = 0; t < 4; ++t) {
        int tk = min(tok0 + t, T - 1);
        const float* lp = logits + (size_t)tk * NUM_EXPERTS + lane * 8;
        float4 x0 = __ldg((const float4*)lp);
        float4 x1 = __ldg((const float4*)(lp + 4));
        float v[8] = {x0.x, x0.y, x0.z, x0.w, x1.x, x1.y, x1.z, x1.w};
        float k[8];
#pragma unroll
        for (int j = 0; j < 8; ++j) k[j] = sigmoid_fast(v[j]) + bb[j];

        float* dst = wk + t * TROW + g_mine * GROW + q * 8;
        *(float4*)dst       = make_float4(k[0], k[1], k[2], k[3]);
        *(float4*)(dst + 4) = make_float4(k[4], k[5], k[6], k[7]);

        float m1 = fmaxf(k[0], k[1]);
        float m2 = fminf(k[0], k[1]);
#pragma unroll
        for (int j = 2; j < 8; ++j) {
            m2 = fmaxf(m2, fminf(m1, k[j]));
            m1 = fmaxf(m1, k[j]);
        }
        // quad butterfly: exact top-2 of the group's 32 (3 FMNMX per step)
#pragma unroll
        for (int m = 1; m < 4; m <<= 1) {
            float o1 = __shfl_xor_sync(0xffffffffu, m1, m);
            float o2 = __shfl_xor_sync(0xffffffffu, m2, m);
            m2 = fmaxf(fminf(m1, o1), fmaxf(m2, o2));
            m1 = fmaxf(m1, o1);
        }
        gs_t[t] = m1 + m2;
    }
    __syncwarp();

    // ---- Octet phase ----
    const int sub = lane & 7;
    const int oct = lane >> 3;

    float g0 = __shfl_sync(0xffffffffu, gs_t[0], sub * 4);
    float g1 = __shfl_sync(0xffffffffu, gs_t[1], sub * 4);
    float g2 = __shfl_sync(0xffffffffu, gs_t[2], sub * 4);
    float g3 = __shfl_sync(0xffffffffu, gs_t[3], sub * 4);
    float gs = (oct == 0) ? g0 : (oct == 1) ? g1 : (oct == 2) ? g2 : g3;

    int rank = 0;
#pragma unroll
    for (int g = 1; g < 8; ++g) {
        float og = __shfl_xor_sync(0xffffffffu, gs, g, 8);
        int osub = sub ^ g;
        rank += (og > gs || (og == gs && osub < sub)) ? 1 : 0;
    }

    unsigned nm = (rank < TOPKG) ? ((unsigned)sub << (rank * 4)) : 0u;
    nm |= __shfl_xor_sync(0xffffffffu, nm, 1, 8);
    nm |= __shfl_xor_sync(0xffffffffu, nm, 2, 8);
    nm |= __shfl_xor_sync(0xffffffffu, nm, 4, 8);
    const int gsel = (nm >> ((sub >> 1) * 4)) & 7;
    const int half = sub & 1;

    // ---- Pass B: keyed top-8 of my 16 keys (distinct per lane) ----
    const float* src = wk + oct * TROW + gsel * GROW + half * 16;
    float4 a0 = *(const float4*)(src);
    float4 a1 = *(const float4*)(src + 4);
    float4 a2 = *(const float4*)(src + 8);
    float4 a3 = *(const float4*)(src + 12);
    const unsigned ibase = (unsigned)(gsel * 32 + half * 16);

    float Ak[8] = {a0.x, a0.y, a0.z, a0.w, a1.x, a1.y, a1.z, a1.w};
    float Bk[8] = {a2.x, a2.y, a2.z, a2.w, a3.x, a3.y, a3.z, a3.w};
    unsigned Ai[8], Bi[8];
#pragma unroll
    for (int j = 0; j < 8; ++j) { Ai[j] = ibase + j; Bi[j] = ibase + 8 + j; }
    sort8(Ak, Ai);
    sort8(Bk, Bi);
    merge8(Ak, Ai, Bk, Bi);                 // sorted top-8 of my 16

    // ---- Merge tree across the octet: distances 1, 2, 4 ----
    // Tie-aware comparator is symmetric -> after each level all lanes in the
    // merged set hold identical lists; after 3 levels, global sorted top-8.
#pragma unroll
    for (int m = 1; m < 8; m <<= 1) {
#pragma unroll
        for (int j = 0; j < 8; ++j) {
            Bk[j] = __shfl_xor_sync(0xffffffffu, Ak[j], m);
            Bi[j] = __shfl_xor_sync(0xffffffffu, Ai[j], m);
        }
        merge8t(Ak, Ai, Bk, Bi);
    }

    // ---- Lane sub muxes out element sub (7+7 SEL tree) ----
    float k0 = (sub & 1) ? Ak[1] : Ak[0];
    float k1 = (sub & 1) ? Ak[3] : Ak[2];
    float k2 = (sub & 1) ? Ak[5] : Ak[4];
    float k3 = (sub & 1) ? Ak[7] : Ak[6];
    unsigned i0 = (sub & 1) ? Ai[1] : Ai[0];
    unsigned i1 = (sub & 1) ? Ai[3] : Ai[2];
    unsigned i2 = (sub & 1) ? Ai[5] : Ai[4];
    unsigned i3 = (sub & 1) ? Ai[7] : Ai[6];
    float ka = (sub & 2) ? k1 : k0;
    float kb = (sub & 2) ? k3 : k2;
    unsigned ia = (sub & 2) ? i1 : i0;
    unsigned ib = (sub & 2) ? i3 : i2;
    float mykey   = (sub & 4) ? kb : ka;
    unsigned myidx = (sub & 4) ? ib : ia;

    // ---- Phase 4: weight = sigmoid score, renormalize, scale ----
    float bvw = __ldg(bias + myidx);
    float score = mykey - bvw;

    float wsum = score;
#pragma unroll
    for (int m = 1; m < 8; m <<= 1)
        wsum += __shfl_xor_sync(0xffffffffu, wsum, m, 8);

    float w = score * __fdividef(ROUTER_SCALE, wsum + 1e-20f);

    if (tok0 + oct < T) {
        size_t o = (size_t)tok0 * TOPK + lane;
        out_w[o] = w;
        if (out_i) out_i[o] = (float)myidx;
    }
}

extern "C" void kernel_launch(void* const* d_in, const int* in_sizes, int n_in,
                              void* d_out, int out_size) {
    const float* logits = (const float*)d_in[0];
    const float* bias   = (n_in > 1) ? (const float*)d_in[1] : nullptr;
    int s0 = in_sizes[0];
    int s1 = (n_in > 1) ? in_sizes[1] : 0;
    if (s0 == NUM_EXPERTS && s1 > NUM_EXPERTS) {
        const float* tp = logits; logits = bias; bias = tp;
        int ts = s0; s0 = s1; s1 = ts;
    }
    int T = s0 / NUM_EXPERTS;

    float* out_w = (float*)d_out;
    float* out_i = (out_size >= T * 2 * TOPK) ? (out_w + (size_t)T * TOPK) : nullptr;

    int tokens_per_block = NWARPS * 4;
    dim3 grid((T + tokens_per_block - 1) / tokens_per_block);
    router_kernel<<<grid, NWARPS * 32>>>(logits, bias, out_w, out_i, T);
}

// round 14
// speedup vs baseline: 1.0340x; 1.0340x over previous
#include <cuda_runtime.h>
#include <math_constants.h>

// LLaDA2 group-limited router, GB300 sm_103a — round 14.
// R7 base. merge8 deleted: each lane spills its TWO sorted 8-lists to a
// 16-deep smem stack (exact orderf keys + idx) and extraction does a lazy
// two-pointer merge per lane + octet redux_max/redux_min per round (the
// exact R9 tie-break). Net ~-75 warp-instrs and -32 shuffles per warp.

#define NUM_EXPERTS 256
#define TOPK 8
#define TOPKG 4
#define ROUTER_SCALE 2.5f

#define GROW 36                 // floats per padded 32-expert group row (144B)
#define TROW (8 * GROW)
#define WROWS (4 * TROW)
#define NWARPS 4                // 128 threads per block

// ---- scalar keyed CE (descending); ties keep first arg ----
static __device__ __forceinline__ void cef(float& ka, unsigned& xa,
                                           float& kb, unsigned& xb) {
    float kx = fmaxf(ka, kb);
    float kn = fminf(ka, kb);
    bool t = (kb > ka);
    unsigned ix = t ? xb : xa;
    unsigned in_ = t ? xa : xb;
    ka = kx; kb = kn; xa = ix; xb = in_;
}

// Batcher 8-input sorting network (19 CE), descending.
static __device__ __forceinline__ void sort8(float k[8], unsigned x[8]) {
    cef(k[0],x[0],k[1],x[1]); cef(k[2],x[2],k[3],x[3]);
    cef(k[4],x[4],k[5],x[5]); cef(k[6],x[6],k[7],x[7]);
    cef(k[0],x[0],k[2],x[2]); cef(k[1],x[1],k[3],x[3]);
    cef(k[4],x[4],k[6],x[6]); cef(k[5],x[5],k[7],x[7]);
    cef(k[1],x[1],k[2],x[2]); cef(k[5],x[5],k[6],x[6]);
    cef(k[0],x[0],k[4],x[4]); cef(k[1],x[1],k[5],x[5]);
    cef(k[2],x[2],k[6],x[6]); cef(k[3],x[3],k[7],x[7]);
    cef(k[2],x[2],k[4],x[4]); cef(k[3],x[3],k[5],x[5]);
    cef(k[1],x[1],k[2],x[2]); cef(k[3],x[3],k[4],x[4]); cef(k[5],x[5],k[6],x[6]);
}

// Exact order-preserving float<->uint (no NaNs in this data).
static __device__ __forceinline__ unsigned orderf(float f) {
    unsigned u = __float_as_uint(f);
    unsigned m = ((unsigned)((int)u >> 31)) | 0x80000000u;
    return u ^ m;
}
static __device__ __forceinline__ float unorderf(unsigned k) {
    unsigned m = (~((unsigned)((int)k >> 31))) | 0x80000000u;
    return __uint_as_float(k ^ m);
}

static __device__ __forceinline__ float sigmoid_fast(float x) {
    float e = __expf(-x);
    float d = 1.0f + e;
    float r;
    asm("rcp.approx.f32 %0, %1;" : "=f"(r) : "f"(d));
    return r;
}

__global__ void __launch_bounds__(128)
router_kernel(const float* __restrict__ logits,
              const float* __restrict__ bias,
              float* __restrict__ out_w,
              float* __restrict__ out_i,
              int T) {
    __shared__ float skey[NWARPS * WROWS];   // 18432 B

    const int warp = threadIdx.x >> 5;
    const int lane = threadIdx.x & 31;
    float* wk = skey + warp * WROWS;

    const int tok0 = blockIdx.x * (NWARPS * 4) + warp * 4;

    float4 bv0 = __ldg((const float4*)(bias + lane * 8));
    float4 bv1 = __ldg((const float4*)(bias + lane * 8 + 4));
    float bb[8] = {bv0.x, bv0.y, bv0.z, bv0.w, bv1.x, bv1.y, bv1.z, bv1.w};

    const int g_mine = lane >> 2;
    const int q = lane & 3;

    // ---- Pass A (coalesced): keys -> smem; exact group top-2 scores ----
    float gs_t[4];
#pragma unroll
    for (int t = 0; t < 4; ++t) {
        int tk = min(tok0 + t, T - 1);
        const float* lp = logits + (size_t)tk * NUM_EXPERTS + lane * 8;
        float4 x0 = __ldg((const float4*)lp);
        float4 x1 = __ldg((const float4*)(lp + 4));
        float v[8] = {x0.x, x0.y, x0.z, x0.w, x1.x, x1.y, x1.z, x1.w};
        float k[8];
#pragma unroll
        for (int j = 0; j < 8; ++j) k[j] = sigmoid_fast(v[j]) + bb[j];

        float* dst = wk + t * TROW + g_mine * GROW + q * 8;
        *(float4*)dst       = make_float4(k[0], k[1], k[2], k[3]);
        *(float4*)(dst + 4) = make_float4(k[4], k[5], k[6], k[7]);

        // exact top-2 of 8 via tournament (union identity: second of union
        // = max(min(max_a,max_b), max(sec_a,sec_b)) — 4-deep chain)
        float x0a = fmaxf(k[0], k[1]), n0 = fminf(k[0], k[1]);
        float x1a = fmaxf(k[2], k[3]), n1 = fminf(k[2], k[3]);
        float x2a = fmaxf(k[4], k[5]), n2 = fminf(k[4], k[5]);
        float x3a = fmaxf(k[6], k[7]), n3 = fminf(k[6], k[7]);
        float X0 = fmaxf(x0a, x1a);
        float N0 = fmaxf(fminf(x0a, x1a), fmaxf(n0, n1));
        float X1 = fmaxf(x2a, x3a);
        float N1 = fmaxf(fminf(x2a, x3a), fmaxf(n2, n3));
        float m1 = fmaxf(X0, X1);
        float m2 = fmaxf(fminf(X0, X1), fmaxf(N0, N1));
        // quad butterfly: exact top-2 of the group's 32 (3 FMNMX per step)
#pragma unroll
        for (int m = 1; m < 4; m <<= 1) {
            float o1 = __shfl_xor_sync(0xffffffffu, m1, m);
            float o2 = __shfl_xor_sync(0xffffffffu, m2, m);
            m2 = fmaxf(fminf(m1, o1), fmaxf(m2, o2));
            m1 = fmaxf(m1, o1);
        }
        gs_t[t] = m1 + m2;
    }
    __syncwarp();

    // ---- Octet phase ----
    const int sub = lane & 7;
    const int oct = lane >> 3;

    float g0 = __shfl_sync(0xffffffffu, gs_t[0], sub * 4);
    float g1 = __shfl_sync(0xffffffffu, gs_t[1], sub * 4);
    float g2 = __shfl_sync(0xffffffffu, gs_t[2], sub * 4);
    float g3 = __shfl_sync(0xffffffffu, gs_t[3], sub * 4);
    float gs = (oct == 0) ? g0 : (oct == 1) ? g1 : (oct == 2) ? g2 : g3;

    int rank = 0;
#pragma unroll
    for (int g = 1; g < 8; ++g) {
        float og = __shfl_xor_sync(0xffffffffu, gs, g, 8);
        int osub = sub ^ g;
        rank += (og > gs || (og == gs && osub < sub)) ? 1 : 0;
    }

    unsigned nm = (rank < TOPKG) ? ((unsigned)sub << (rank * 4)) : 0u;
    nm |= __shfl_xor_sync(0xffffffffu, nm, 1, 8);
    nm |= __shfl_xor_sync(0xffffffffu, nm, 2, 8);
    nm |= __shfl_xor_sync(0xffffffffu, nm, 4, 8);
    const int gsel = (nm >> ((sub >> 1) * 4)) & 7;
    const int half = sub & 1;

    // ---- Pass B: two sorted 8-lists of my 16 keys (NO merge) ----
    const float* src = wk + oct * TROW + gsel * GROW + half * 16;
    float4 a0 = *(const float4*)(src);
    float4 a1 = *(const float4*)(src + 4);
    float4 a2 = *(const float4*)(src + 8);
    float4 a3 = *(const float4*)(src + 12);
    const unsigned ibase = (unsigned)(gsel * 32 + half * 16);

    float Ak[8] = {a0.x, a0.y, a0.z, a0.w, a1.x, a1.y, a1.z, a1.w};
    float Bk[8] = {a2.x, a2.y, a2.z, a2.w, a3.x, a3.y, a3.z, a3.w};
    unsigned Ai[8], Bi[8];
#pragma unroll
    for (int j = 0; j < 8; ++j) { Ai[j] = ibase + j; Bi[j] = ibase + 8 + j; }
    sort8(Ak, Ai);
    sort8(Bk, Bi);

    // ---- Spill both sorted lists to smem stacks (slot-major) ----
    // Region is fully consumed (values in registers); syncwarp orders reads
    // before the overwriting stores. 16 slots x 32 lanes x 8B = 4096B <= 4608B.
    __syncwarp();
    unsigned long long* stk = (unsigned long long*)wk;
#pragma unroll
    for (int j = 0; j < 8; ++j) {
        stk[j * 32 + lane]       = ((unsigned long long)orderf(Ak[j]) << 32) | Ai[j];
        stk[(8 + j) * 32 + lane] = ((unsigned long long)orderf(Bk[j]) << 32) | Bi[j];
    }
    __syncwarp();

    // ---- Extraction: lazy two-pointer merge + octet redux per round ----
    // Bounds: at most 7 pops of one list can precede the final compare, so
    // pointers never run past their own 8-slot region before the loop ends.
    const unsigned long long* pa = stk + lane;            // list A head
    const unsigned long long* pb = stk + 8 * 32 + lane;   // list B head
    unsigned long long hA = *pa;
    unsigned long long hB = *pb;
    const unsigned octmask = 0xFFu << (oct * 8);
    unsigned mok = 0u, myidx = 0u;
#pragma unroll
    for (int r = 0; r < TOPK; ++r) {
        unsigned aK = (unsigned)(hA >> 32), aI = (unsigned)hA;
        unsigned bK = (unsigned)(hB >> 32), bI = (unsigned)hB;
        bool useA = (aK > bK) || (aK == bK && aI < bI);
        unsigned hk = useA ? aK : bK;
        unsigned hi = useA ? aI : bI;
        unsigned m = __reduce_max_sync(octmask, hk);
        unsigned cand = (hk == m) ? hi : 0xFFFFFFFFu;
        unsigned imin = __reduce_min_sync(octmask, cand);
        if (sub == r) { mok = m; myidx = imin; }
        bool win = (cand == imin);           // idx unique -> exactly one lane
        if (win && useA)  { pa += 32; hA = *pa; }
        if (win && !useA) { pb += 32; hB = *pb; }
    }

    // ---- Phase 4: weight = sigmoid score, renormalize, scale ----
    float mykey = unorderf(mok);
    float bvw = __ldg(bias + myidx);
    float score = mykey - bvw;

    float wsum = score;
#pragma unroll
    for (int m = 1; m < 8; m <<= 1)
        wsum += __shfl_xor_sync(0xffffffffu, wsum, m, 8);

    float w = score * __fdividef(ROUTER_SCALE, wsum + 1e-20f);

    if (tok0 + oct < T) {
        size_t o = (size_t)tok0 * TOPK + lane;
        out_w[o] = w;
        if (out_i) out_i[o] = (float)myidx;
    }
}

extern "C" void kernel_launch(void* const* d_in, const int* in_sizes, int n_in,
                              void* d_out, int out_size) {
    const float* logits = (const float*)d_in[0];
    const float* bias   = (n_in > 1) ? (const float*)d_in[1] : nullptr;
    int s0 = in_sizes[0];
    int s1 = (n_in > 1) ? in_sizes[1] : 0;
    if (s0 == NUM_EXPERTS && s1 > NUM_EXPERTS) {
        const float* tp = logits; logits = bias; bias = tp;
        int ts = s0; s0 = s1; s1 = ts;
    }
    int T = s0 / NUM_EXPERTS;

    float* out_w = (float*)d_out;
    float* out_i = (out_size >= T * 2 * TOPK) ? (out_w + (size_t)T * TOPK) : nullptr;

    int tokens_per_block = NWARPS * 4;
    dim3 grid((T + tokens_per_block - 1) / tokens_per_block);
    router_kernel<<<grid, NWARPS * 32>>>(logits, bias, out_w, out_i, T);
}

// round 15
// speedup vs baseline: 1.1153x; 1.0786x over previous
#include <cuda_runtime.h>
#include <math_constants.h>

// LLaDA2 group-limited router, GB300 sm_103a — round 15.
// R7 (best: 57.0us) specialized at LAUNCH time: when T is a multiple of
// tokens-per-block (always true for T=131072), run a no-tail kernel with
// no per-iteration clamp and unconditional stores. Fallback = exact R7.

#define NUM_EXPERTS 256
#define TOPK 8
#define TOPKG 4
#define ROUTER_SCALE 2.5f
#define NEG_INF (-CUDART_INF_F)

#define GROW 36                 // floats per padded 32-expert group row (144B)
#define TROW (8 * GROW)
#define WROWS (4 * TROW)
#define NWARPS 4                // 128 threads per block

// ---- scalar keyed CE (descending); ties keep first arg ----
static __device__ __forceinline__ void cef(float& ka, unsigned& xa,
                                           float& kb, unsigned& xb) {
    float kx = fmaxf(ka, kb);
    float kn = fminf(ka, kb);
    bool t = (kb > ka);
    unsigned ix = t ? xb : xa;
    unsigned in_ = t ? xa : xb;
    ka = kx; kb = kn; xa = ix; xb = in_;
}
static __device__ __forceinline__ void maxsel(float& lk, unsigned& li,
                                              float ck, unsigned ci) {
    bool t = (ck > lk);
    lk = fmaxf(lk, ck);
    li = t ? ci : li;
}

// Batcher 8-input sorting network (19 CE), descending.
static __device__ __forceinline__ void sort8(float k[8], unsigned x[8]) {
    cef(k[0],x[0],k[1],x[1]); cef(k[2],x[2],k[3],x[3]);
    cef(k[4],x[4],k[5],x[5]); cef(k[6],x[6],k[7],x[7]);
    cef(k[0],x[0],k[2],x[2]); cef(k[1],x[1],k[3],x[3]);
    cef(k[4],x[4],k[6],x[6]); cef(k[5],x[5],k[7],x[7]);
    cef(k[1],x[1],k[2],x[2]); cef(k[5],x[5],k[6],x[6]);
    cef(k[0],x[0],k[4],x[4]); cef(k[1],x[1],k[5],x[5]);
    cef(k[2],x[2],k[6],x[6]); cef(k[3],x[3],k[7],x[7]);
    cef(k[2],x[2],k[4],x[4]); cef(k[3],x[3],k[5],x[5]);
    cef(k[1],x[1],k[2],x[2]); cef(k[3],x[3],k[4],x[4]); cef(k[5],x[5],k[6],x[6]);
}

// L := top-8 of L ∪ C (both sorted desc): 8 max-selects + 12-CE bitonic clean.
static __device__ __forceinline__ void merge8(float Lk[8], unsigned Li[8],
                                              const float Ck[8], const unsigned Ci[8]) {
#pragma unroll
    for (int i = 0; i < 8; ++i) maxsel(Lk[i], Li[i], Ck[7 - i], Ci[7 - i]);
    cef(Lk[0],Li[0],Lk[4],Li[4]); cef(Lk[1],Li[1],Lk[5],Li[5]);
    cef(Lk[2],Li[2],Lk[6],Li[6]); cef(Lk[3],Li[3],Lk[7],Li[7]);
    cef(Lk[0],Li[0],Lk[2],Li[2]); cef(Lk[1],Li[1],Lk[3],Li[3]);
    cef(Lk[4],Li[4],Lk[6],Li[6]); cef(Lk[5],Li[5],Lk[7],Li[7]);
    cef(Lk[0],Li[0],Lk[1],Li[1]); cef(Lk[2],Li[2],Lk[3],Li[3]);
    cef(Lk[4],Li[4],Lk[5],Li[5]); cef(Lk[6],Li[6],Lk[7],Li[7]);
}

static __device__ __forceinline__ float sigmoid_fast(float x) {
    float e = __expf(-x);
    float d = 1.0f + e;
    float r;
    asm("rcp.approx.f32 %0, %1;" : "=f"(r) : "f"(d));
    return r;
}

// Shared body. CLAMPED=false assumes tok0+4 <= T for every warp and stores
// unconditionally; CLAMPED=true is the exact R7 path.
template <bool CLAMPED>
static __device__ __forceinline__ void router_body(
    const float* __restrict__ logits,
    const float* __restrict__ bias,
    float* __restrict__ out_w,
    float* __restrict__ out_i,
    int T, float* skey) {

    const int warp = threadIdx.x >> 5;
    const int lane = threadIdx.x & 31;
    float* wk = skey + warp * WROWS;

    const int tok0 = blockIdx.x * (NWARPS * 4) + warp * 4;

    float4 bv0 = __ldg((const float4*)(bias + lane * 8));
    float4 bv1 = __ldg((const float4*)(bias + lane * 8 + 4));
    float bb[8] = {bv0.x, bv0.y, bv0.z, bv0.w, bv1.x, bv1.y, bv1.z, bv1.w};

    const int g_mine = lane >> 2;
    const int q = lane & 3;

    // ---- Pass A (coalesced): keys -> smem; exact group top-2 scores ----
    const float* lp0 = logits + (size_t)tok0 * NUM_EXPERTS + lane * 8;
    float gs_t[4];
#pragma unroll
    for (int t = 0; t < 4; ++t) {
        const float* lp;
        if (CLAMPED) {
            int tk = min(tok0 + t, T - 1);
            lp = logits + (size_t)tk * NUM_EXPERTS + lane * 8;
        } else {
            lp = lp0 + t * NUM_EXPERTS;
        }
        float4 x0 = __ldg((const float4*)lp);
        float4 x1 = __ldg((const float4*)(lp + 4));
        float v[8] = {x0.x, x0.y, x0.z, x0.w, x1.x, x1.y, x1.z, x1.w};
        float k[8];
#pragma unroll
        for (int j = 0; j < 8; ++j) k[j] = sigmoid_fast(v[j]) + bb[j];

        float* dst = wk + t * TROW + g_mine * GROW + q * 8;
        *(float4*)dst       = make_float4(k[0], k[1], k[2], k[3]);
        *(float4*)(dst + 4) = make_float4(k[4], k[5], k[6], k[7]);

        float m1 = fmaxf(k[0], k[1]);
        float m2 = fminf(k[0], k[1]);
#pragma unroll
        for (int j = 2; j < 8; ++j) {
            m2 = fmaxf(m2, fminf(m1, k[j]));
            m1 = fmaxf(m1, k[j]);
        }
        // quad butterfly: exact top-2 of the group's 32 (3 FMNMX per step)
#pragma unroll
        for (int m = 1; m < 4; m <<= 1) {
            float o1 = __shfl_xor_sync(0xffffffffu, m1, m);
            float o2 = __shfl_xor_sync(0xffffffffu, m2, m);
            m2 = fmaxf(fminf(m1, o1), fmaxf(m2, o2));
            m1 = fmaxf(m1, o1);
        }
        gs_t[t] = m1 + m2;
    }
    __syncwarp();

    // ---- Octet phase ----
    const int sub = lane & 7;
    const int oct = lane >> 3;

    float g0 = __shfl_sync(0xffffffffu, gs_t[0], sub * 4);
    float g1 = __shfl_sync(0xffffffffu, gs_t[1], sub * 4);
    float g2 = __shfl_sync(0xffffffffu, gs_t[2], sub * 4);
    float g3 = __shfl_sync(0xffffffffu, gs_t[3], sub * 4);
    float gs = (oct == 0) ? g0 : (oct == 1) ? g1 : (oct == 2) ? g2 : g3;

    int rank = 0;
#pragma unroll
    for (int g = 1; g < 8; ++g) {
        float og = __shfl_xor_sync(0xffffffffu, gs, g, 8);
        int osub = sub ^ g;
        rank += (og > gs || (og == gs && osub < sub)) ? 1 : 0;
    }

    unsigned nm = (rank < TOPKG) ? ((unsigned)sub << (rank * 4)) : 0u;
    nm |= __shfl_xor_sync(0xffffffffu, nm, 1, 8);
    nm |= __shfl_xor_sync(0xffffffffu, nm, 2, 8);
    nm |= __shfl_xor_sync(0xffffffffu, nm, 4, 8);
    const int gsel = (nm >> ((sub >> 1) * 4)) & 7;
    const int half = sub & 1;

    // ---- Pass B: keyed top-8 of my 16 keys (distinct per lane) ----
    const float* src = wk + oct * TROW + gsel * GROW + half * 16;
    float4 a0 = *(const float4*)(src);
    float4 a1 = *(const float4*)(src + 4);
    float4 a2 = *(const float4*)(src + 8);
    float4 a3 = *(const float4*)(src + 12);
    const unsigned ibase = (unsigned)(gsel * 32 + half * 16);

    float Ak[8] = {a0.x, a0.y, a0.z, a0.w, a1.x, a1.y, a1.z, a1.w};
    float Bk[8] = {a2.x, a2.y, a2.z, a2.w, a3.x, a3.y, a3.z, a3.w};
    unsigned Ai[8], Bi[8];
#pragma unroll
    for (int j = 0; j < 8; ++j) { Ai[j] = ibase + j; Bi[j] = ibase + 8 + j; }
    sort8(Ak, Ai);
    sort8(Bk, Bi);
    merge8(Ak, Ai, Bk, Bi);                 // sorted top-8 of my 16

    // ---- Extraction: global top-8 across 8 distinct lists (masks 1,2,4) ----
    float mykey = 0.0f; unsigned myidx = 0u;
#pragma unroll
    for (int r = 0; r < TOPK; ++r) {
        float hk = Ak[0]; unsigned hi = Ai[0];
#pragma unroll
        for (int m = 1; m < 8; m <<= 1) {
            float ok    = __shfl_xor_sync(0xffffffffu, hk, m, 8);
            unsigned oi = __shfl_xor_sync(0xffffffffu, hi, m, 8);
            bool take = (ok > hk) || (ok == hk && oi < hi);
            hk = take ? ok : hk;
            hi = take ? oi : hi;
        }
        if (sub == r) { mykey = hk; myidx = hi; }
        bool win = (hi == Ai[0]);           // ids unique -> exactly one lane
#pragma unroll
        for (int j = 0; j < 7 - r; ++j) {
            Ak[j] = win ? Ak[j + 1] : Ak[j];
            Ai[j] = win ? Ai[j + 1] : Ai[j];
        }
        if (r == 0) Ak[7] = win ? NEG_INF : Ak[7];
    }

    // ---- Phase 4: weight = sigmoid score, renormalize, scale ----
    float bvw = __ldg(bias + myidx);
    float score = mykey - bvw;

    float wsum = score;
#pragma unroll
    for (int m = 1; m < 8; m <<= 1)
        wsum += __shfl_xor_sync(0xffffffffu, wsum, m, 8);

    float w = score * __fdividef(ROUTER_SCALE, wsum + 1e-20f);

    if (!CLAMPED || (tok0 + oct < T)) {
        size_t o = (size_t)tok0 * TOPK + lane;
        out_w[o] = w;
        if (out_i) out_i[o] = (float)myidx;
    }
}

__global__ void __launch_bounds__(128)
router_kernel_exact(const float* __restrict__ logits,
                    const float* __restrict__ bias,
                    float* __restrict__ out_w,
                    float* __restrict__ out_i,
                    int T) {
    __shared__ float skey[NWARPS * WROWS];
    router_body<false>(logits, bias, out_w, out_i, T, skey);
}

__global__ void __launch_bounds__(128)
router_kernel_tail(const float* __restrict__ logits,
                   const float* __restrict__ bias,
                   float* __restrict__ out_w,
                   float* __restrict__ out_i,
                   int T) {
    __shared__ float skey[NWARPS * WROWS];
    router_body<true>(logits, bias, out_w, out_i, T, skey);
}

extern "C" void kernel_launch(void* const* d_in, const int* in_sizes, int n_in,
                              void* d_out, int out_size) {
    const float* logits = (const float*)d_in[0];
    const float* bias   = (n_in > 1) ? (const float*)d_in[1] : nullptr;
    int s0 = in_sizes[0];
    int s1 = (n_in > 1) ? in_sizes[1] : 0;
    if (s0 == NUM_EXPERTS && s1 > NUM_EXPERTS) {
        const float* tp = logits; logits = bias; bias = tp;
        int ts = s0; s0 = s1; s1 = ts;
    }
    int T = s0 / NUM_EXPERTS;

    float* out_w = (float*)d_out;
    float* out_i = (out_size >= T * 2 * TOPK) ? (out_w + (size_t)T * TOPK) : nullptr;

    int tokens_per_block = NWARPS * 4;          // 16
    dim3 grid((T + tokens_per_block - 1) / tokens_per_block);
    if (T % tokens_per_block == 0) {
        router_kernel_exact<<<grid, NWARPS * 32>>>(logits, bias, out_w, out_i, T);
    } else {
        router_kernel_tail<<<grid, NWARPS * 32>>>(logits, bias, out_w, out_i, T);
    }
}